// round 16
// baseline (speedup 1.0000x reference)
#include <cuda_runtime.h>
#include <cooperative_groups.h>
namespace cg = cooperative_groups;

#define NN 100000
#define NE 1200000
#define D 64
#define NL 3
#define NM 5000
#define NO 24
#define BN_EPS 1e-5f
#define NB_SCAN ((NN + 1023) / 1024)
#define HS 68
#define COOP_BLOCKS 592
#define SMEM_WB (2 * 2048 * 8)                   // 32768 B (W fragments hi+lo)
#define RPB_GA 80
#define NT_GA  320
#define SMEM_GA (RPB_GA * HS * 4 + SMEM_WB)      // 54528 B (gather path, 4 blocks/SM)
#define RPB_NG 128
#define NT_NG  256

typedef unsigned long long ull;

// ---------------- scratch ----------------
__device__ __align__(128) float g_X0 [NN * D];
__device__ __align__(128) float g_T  [NN * D];
__device__ __align__(128) float g_XS [NL * NN * D];
__device__ __align__(128) float g_G  [NM * D];
__device__ __align__(128) float g_TG [NM * D];
__device__ __align__(128) float g_stats[4 * 2 * D];
__device__ __align__(128) int g_deg   [NN];
__device__ __align__(128) int g_cur   [NN];
__device__ __align__(128) int g_rowptr[NN + 1];
__device__ __align__(128) int g_csr   [NE];      // stores src*64 (pre-scaled)
__device__ __align__(128) int g_bsum  [NB_SCAN];
__device__ __align__(128) int g_boff  [NB_SCAN];
__device__ __align__(128) int g_molptr[NM + 1];

// ---------------- helpers ----------------
__device__ __forceinline__ uint32_t cvt_tf32(float x) {
    uint32_t r; asm("cvt.rna.tf32.f32 %0, %1;" : "=r"(r) : "f"(x)); return r;
}
__device__ __forceinline__ void mma_tf32(float* c, uint32_t a0, uint32_t a1,
                                         uint32_t a2, uint32_t a3,
                                         uint32_t b0, uint32_t b1) {
    asm volatile(
        "mma.sync.aligned.m16n8k8.row.col.f32.tf32.tf32.f32 "
        "{%0,%1,%2,%3},{%4,%5,%6,%7},{%8,%9},{%0,%1,%2,%3};"
        : "+f"(c[0]), "+f"(c[1]), "+f"(c[2]), "+f"(c[3])
        : "r"(a0), "r"(a1), "r"(a2), "r"(a3), "r"(b0), "r"(b1));
}

// ---------------- init ----------------
__global__ void k_init() {
    int t = blockIdx.x * blockDim.x + threadIdx.x;
    if (t < NN) { g_deg[t] = 0; g_cur[t] = 0; }
    if (t < 4 * 2 * D) g_stats[t] = 0.f;
}

__global__ void k_embed(const int* __restrict__ atom_ids, const float* __restrict__ embW) {
    int t = blockIdx.x * blockDim.x + threadIdx.x;
    if (t >= NN * 16) return;
    int n = t >> 4, c = (t & 15) << 2;
    int a = __ldg(atom_ids + n);
    *(float4*)(g_X0 + (size_t)n * D + c) = *(const float4*)(embW + (size_t)a * D + c);
}

// ---------------- cooperative CSR build -----------------
__global__ void k_csr_coop(const int* __restrict__ src, const int* __restrict__ dst) {
    cg::grid_group grid = cg::this_grid();
    int tid = threadIdx.x, bid = blockIdx.x;
    int gt = bid * 256 + tid, gs = gridDim.x * 256;

    for (int e = gt; e < NE; e += gs) atomicAdd(&g_deg[__ldg(dst + e)], 1);
    grid.sync();

    __shared__ int sh[256];
    if (bid < NB_SCAN) {
        int base = bid * 1024;
        int loc[4]; int s = 0;
        #pragma unroll
        for (int j = 0; j < 4; j++) {
            int i = base + tid * 4 + j;
            int v = (i < NN) ? g_deg[i] : 0;
            s += v; loc[j] = s;
        }
        int excl_in = s;
        sh[tid] = excl_in; __syncthreads();
        for (int off = 1; off < 256; off <<= 1) {
            int t2 = (tid >= off) ? sh[tid - off] : 0;
            __syncthreads();
            sh[tid] += t2;
            __syncthreads();
        }
        int pre = sh[tid] - excl_in;
        #pragma unroll
        for (int j = 0; j < 4; j++) {
            int i = base + tid * 4 + j;
            if (i < NN) g_rowptr[i + 1] = pre + loc[j];
        }
        if (tid == 255) g_bsum[bid] = sh[255];
    }
    grid.sync();

    if (bid == 0 && tid < 32) {
        int carry = 0;
        for (int b = 0; b < NB_SCAN; b += 32) {
            int idx = b + tid;
            int v = (idx < NB_SCAN) ? g_bsum[idx] : 0;
            int x = v;
            #pragma unroll
            for (int off = 1; off < 32; off <<= 1) {
                int y = __shfl_up_sync(0xffffffff, x, off);
                if (tid >= off) x += y;
            }
            if (idx < NB_SCAN) g_boff[idx] = carry + x - v;
            carry += __shfl_sync(0xffffffff, x, 31);
        }
    }
    grid.sync();

    if (gt == 0) g_rowptr[0] = 0;
    for (int i = gt; i < NN; i += gs) g_rowptr[i + 1] += g_boff[i >> 10];
    grid.sync();

    for (int e = gt; e < NE; e += gs) {
        int d = __ldg(dst + e);
        int pos = g_rowptr[d] + atomicAdd(&g_cur[d], 1);
        g_csr[pos] = __ldg(src + e) << 6;      // pre-scaled by D
    }
}

__global__ void k_molptr(const int* __restrict__ mol) {
    int t = blockIdx.x * blockDim.x + threadIdx.x;
    if (t >= NN) return;
    int m1 = __ldg(mol + t);
    int m0 = (t == 0) ? -1 : __ldg(mol + t - 1);
    for (int m = m0 + 1; m <= m1; m++) g_molptr[m] = t;
    if (t == NN - 1)
        for (int m = m1 + 1; m <= NM; m++) g_molptr[m] = NN;
}

// ============================================================================
// Unified GEMM kernel (mma.sync tf32, 3xTF32), parametrized block geometry.
// ============================================================================
template<int NT, int MINB, int RPBt, int GATHER, int IN_BN, int OUT_RELU, int STATS, int NPASS>
__global__ __launch_bounds__(NT, MINB) void k_gemm(
    const float* __restrict__ X, const float* __restrict__ W,
    const float* __restrict__ bias, float* __restrict__ O, int rows,
    const float* __restrict__ statsIn, float* __restrict__ statsOut,
    const float* __restrict__ gg, const float* __restrict__ be, float inv_n,
    size_t xStride, size_t wStride)
{
    constexpr int NWARP = NT / 32;
    constexpr int NMT   = RPBt / 16;
    constexpr int WPT   = NWARP / NMT;
    constexpr int NTN   = 8 / WPT;

    extern __shared__ __align__(16) float dsm[];
    float* Hs  = dsm;
    ull*   WBh = (ull*)(GATHER ? (dsm + RPBt * HS) : dsm);
    ull*   WBl = WBh + 2048;
    __shared__ float ssa[D], ssb[D];
    __shared__ float sbuf[2 * D];
    __shared__ int   rp[RPB_NG + 1];
    int tid = threadIdx.x;
    int base = blockIdx.x * RPBt;
    int w = tid >> 5, l = tid & 31;
    int g = l >> 2, t = l & 3;
    int mt = w / WPT, nt0 = (w % WPT) * NTN;

    if (IN_BN && tid < D) {
        float mu  = statsIn[tid] * inv_n;
        float var = statsIn[D + tid] * inv_n - mu * mu;
        float rs  = rsqrtf(var + BN_EPS);
        float a   = rs * gg[tid];
        ssa[tid] = a; ssb[tid] = be[tid] - mu * a;
    }
    if (STATS && tid < 2 * D) sbuf[tid] = 0.f;
    if (GATHER && tid <= RPBt) {
        int node = base + tid;
        rp[tid] = (node <= rows) ? __ldg(&g_rowptr[node]) : 0;
    }

    float c[NTN][4];
    #pragma unroll
    for (int q = 0; q < NTN; q++) {
        float2 b2 = *(const float2*)(bias + (nt0 + q) * 8 + 2 * t);
        c[q][0] = b2.x; c[q][1] = b2.y; c[q][2] = b2.x; c[q][3] = b2.y;
    }

    int r0g = base + mt * 16 + g, r1g = r0g + 8;
    bool v0 = (r0g < rows), v1 = (r1g < rows);

    for (int ps = 0; ps < NPASS; ps++) {
        __syncthreads();
        // ---- stage W fragments ----
        {
            const float* Wp = W + (size_t)ps * wStride;
            for (int i = tid; i < 2048; i += NT) {
                int ent = i >> 5, ll = i & 31;
                int ks = ent >> 3, nt = ent & 7;
                int k0 = ks * 8 + (ll & 3), n = nt * 8 + (ll >> 2);
                float w0 = __ldg(&Wp[k0 * D + n]);
                float w1 = __ldg(&Wp[(k0 + 4) * D + n]);
                uint32_t h0 = cvt_tf32(w0), h1 = cvt_tf32(w1);
                uint32_t l0 = cvt_tf32(w0 - __uint_as_float(h0));
                uint32_t l1 = cvt_tf32(w1 - __uint_as_float(h1));
                WBh[i] = (ull)h0 | ((ull)h1 << 32);
                WBl[i] = (ull)l0 | ((ull)l1 << 32);
            }
        }
        // ---- stage Hs (gather) ----
        if (GATHER) {
            constexpr int NPB = NT / 16;
            constexpr int NB  = RPBt * 16 / NT;
            int cc = (tid & 15) << 2;
            #pragma unroll
            for (int b = 0; b < NB; b++) {
                int n = b * NPB + (tid >> 4);
                int node = base + n;
                if (node < rows) {
                    int beg = rp[n], end = rp[n + 1];
                    float4 acc = *(const float4*)(X + (size_t)node * D + cc);
                    int e = beg;
                    int i0, i1, i2, i3;
                    bool have = (e + 3 < end);
                    if (have) {
                        i0 = __ldg(&g_csr[e]);     i1 = __ldg(&g_csr[e + 1]);
                        i2 = __ldg(&g_csr[e + 2]); i3 = __ldg(&g_csr[e + 3]);
                    }
                    while (have) {
                        int en = e + 4;
                        bool hn = (en + 3 < end);
                        int j0, j1, j2, j3;
                        if (hn) {
                            j0 = __ldg(&g_csr[en]);     j1 = __ldg(&g_csr[en + 1]);
                            j2 = __ldg(&g_csr[en + 2]); j3 = __ldg(&g_csr[en + 3]);
                        }
                        float4 v0f = *(const float4*)(X + (size_t)(i0 + cc));
                        float4 v1f = *(const float4*)(X + (size_t)(i1 + cc));
                        float4 v2f = *(const float4*)(X + (size_t)(i2 + cc));
                        float4 v3f = *(const float4*)(X + (size_t)(i3 + cc));
                        acc.x += (v0f.x + v1f.x) + (v2f.x + v3f.x);
                        acc.y += (v0f.y + v1f.y) + (v2f.y + v3f.y);
                        acc.z += (v0f.z + v1f.z) + (v2f.z + v3f.z);
                        acc.w += (v0f.w + v1f.w) + (v2f.w + v3f.w);
                        e = en; have = hn;
                        i0 = j0; i1 = j1; i2 = j2; i3 = j3;
                    }
                    for (; e < end; e++) {
                        int s0 = __ldg(&g_csr[e]);
                        float4 v0f = *(const float4*)(X + (size_t)(s0 + cc));
                        acc.x += v0f.x; acc.y += v0f.y; acc.z += v0f.z; acc.w += v0f.w;
                    }
                    *(float4*)(Hs + n * HS + cc) = acc;
                }
            }
        }
        __syncthreads();

        // ---- MMA mainloop ----
        const float* ar0 = GATHER ? (Hs + (mt * 16 + g) * HS) : nullptr;
        const float* ar1 = GATHER ? (ar0 + 8 * HS) : nullptr;
        const float* Xr0 = GATHER ? nullptr : (X + (size_t)ps * xStride + (size_t)r0g * D);
        const float* Xr1 = GATHER ? nullptr : (X + (size_t)ps * xStride + (size_t)r1g * D);
        #pragma unroll
        for (int ks = 0; ks < 8; ks++) {
            int kc = ks * 8 + t;
            float x00, x01, x10, x11;
            if (GATHER) {
                x00 = ar0[kc]; x01 = ar0[kc + 4];
                x10 = ar1[kc]; x11 = ar1[kc + 4];
            } else {
                x00 = v0 ? __ldg(Xr0 + kc)     : 0.f;
                x01 = v0 ? __ldg(Xr0 + kc + 4) : 0.f;
                x10 = v1 ? __ldg(Xr1 + kc)     : 0.f;
                x11 = v1 ? __ldg(Xr1 + kc + 4) : 0.f;
                if (IN_BN) {
                    x00 = fmaxf(x00 * ssa[kc]     + ssb[kc],     0.f);
                    x01 = fmaxf(x01 * ssa[kc + 4] + ssb[kc + 4], 0.f);
                    x10 = fmaxf(x10 * ssa[kc]     + ssb[kc],     0.f);
                    x11 = fmaxf(x11 * ssa[kc + 4] + ssb[kc + 4], 0.f);
                }
            }
            uint32_t ah0 = cvt_tf32(x00), ah1 = cvt_tf32(x10);
            uint32_t ah2 = cvt_tf32(x01), ah3 = cvt_tf32(x11);
            uint32_t al0 = cvt_tf32(x00 - __uint_as_float(ah0));
            uint32_t al1 = cvt_tf32(x10 - __uint_as_float(ah1));
            uint32_t al2 = cvt_tf32(x01 - __uint_as_float(ah2));
            uint32_t al3 = cvt_tf32(x11 - __uint_as_float(ah3));
            #pragma unroll
            for (int q = 0; q < NTN; q++) {
                int nt = nt0 + q;
                ull bh = WBh[(ks * 8 + nt) * 32 + l];
                ull bl = WBl[(ks * 8 + nt) * 32 + l];
                uint32_t bh0 = (uint32_t)bh, bh1 = (uint32_t)(bh >> 32);
                uint32_t bl0 = (uint32_t)bl, bl1 = (uint32_t)(bl >> 32);
                mma_tf32(c[q], ah0, ah1, ah2, ah3, bh0, bh1);
                mma_tf32(c[q], al0, al1, al2, al3, bh0, bh1);
                mma_tf32(c[q], ah0, ah1, ah2, ah3, bl0, bl1);
            }
        }
    }

    // ---- store ----
    #pragma unroll
    for (int q = 0; q < NTN; q++) {
        int col = (nt0 + q) * 8 + 2 * t;
        if (v0) {
            float2 o = make_float2(c[q][0], c[q][1]);
            if (OUT_RELU) { o.x = fmaxf(o.x, 0.f); o.y = fmaxf(o.y, 0.f); }
            *(float2*)(O + (size_t)r0g * D + col) = o;
        }
        if (v1) {
            float2 o = make_float2(c[q][2], c[q][3]);
            if (OUT_RELU) { o.x = fmaxf(o.x, 0.f); o.y = fmaxf(o.y, 0.f); }
            *(float2*)(O + (size_t)r1g * D + col) = o;
        }
    }

    if (STATS) {
        #pragma unroll
        for (int q = 0; q < NTN; q++) {
            float e0 = v0 ? c[q][0] : 0.f, e1 = v0 ? c[q][1] : 0.f;
            float e2 = v1 ? c[q][2] : 0.f, e3 = v1 ? c[q][3] : 0.f;
            float s0 = e0 + e2, s1 = e1 + e3;
            float q0 = e0 * e0 + e2 * e2, q1 = e1 * e1 + e3 * e3;
            #pragma unroll
            for (int off = 4; off < 32; off <<= 1) {
                s0 += __shfl_xor_sync(0xffffffff, s0, off);
                s1 += __shfl_xor_sync(0xffffffff, s1, off);
                q0 += __shfl_xor_sync(0xffffffff, q0, off);
                q1 += __shfl_xor_sync(0xffffffff, q1, off);
            }
            if (l < 4) {
                int col = (nt0 + q) * 8 + 2 * t;
                atomicAdd(&sbuf[col],         s0);
                atomicAdd(&sbuf[col + 1],     s1);
                atomicAdd(&sbuf[D + col],     q0);
                atomicAdd(&sbuf[D + col + 1], q1);
            }
        }
        __syncthreads();
        if (tid < 2 * D) atomicAdd(&statsOut[tid], sbuf[tid]);
    }
}

// segmented pool
__global__ void k_pool_seg(const float* __restrict__ XJ) {
    int t = blockIdx.x * 256 + threadIdx.x;
    int m = t >> 4;
    if (m >= NM) return;
    int c = (t & 15) << 2;
    int beg = g_molptr[m], end = g_molptr[m + 1];
    float4 acc = make_float4(0.f, 0.f, 0.f, 0.f);
    for (int n = beg; n < end; n++) {
        float4 v = *(const float4*)(XJ + (size_t)n * D + c);
        acc.x += v.x; acc.y += v.y; acc.z += v.z; acc.w += v.w;
    }
    *(float4*)(g_G + (size_t)m * D + c) = acc;
}

// out = relu(TG*bn) @ (W2 @ oW) + (b2 @ oW + ob)
__global__ __launch_bounds__(256) void k_final(
    const float* __restrict__ W2, const float* __restrict__ oW,
    const float* __restrict__ b2, const float* __restrict__ ob,
    const float* __restrict__ gg, const float* __restrict__ be,
    float* __restrict__ out, int rows)
{
    __shared__ float Ws[D * NO];
    __shared__ float bcs[NO], sa[D], sb[D];
    int tid = threadIdx.x;
    const float* statsIn = g_stats + 3 * 2 * D;
    for (int i = tid; i < D * NO; i += 256) {
        int k = i / NO, o = i % NO;
        float sum = 0.f;
        for (int j = 0; j < D; j++) sum += W2[k * D + j] * oW[j * NO + o];
        Ws[i] = sum;
    }
    if (tid < NO) {
        float sum = ob[tid];
        for (int j = 0; j < D; j++) sum += b2[j] * oW[j * NO + tid];
        bcs[tid] = sum;
    }
    if (tid < D) {
        float mu  = statsIn[tid] * (1.0f / NM);
        float var = statsIn[D + tid] * (1.0f / NM) - mu * mu;
        float rs  = rsqrtf(var + BN_EPS);
        float a   = rs * gg[tid];
        sa[tid] = a; sb[tid] = be[tid] - mu * a;
    }
    __syncthreads();
    int row = blockIdx.x * 256 + tid;
    if (row >= rows) return;
    float acc[NO];
    #pragma unroll
    for (int o = 0; o < NO; o++) acc[o] = bcs[o];
    const float* tr = g_TG + (size_t)row * D;
    for (int k = 0; k < D; k++) {
        float h = fmaxf(tr[k] * sa[k] + sb[k], 0.f);
        #pragma unroll
        for (int o = 0; o < NO; o++) acc[o] += h * Ws[k * NO + o];
    }
    float* orow = out + (size_t)row * NO;
    #pragma unroll
    for (int o = 0; o < NO; o++) orow[o] = acc[o];
}

// ---------------- host ----------------
extern "C" void kernel_launch(void* const* d_in, const int* in_sizes, int n_in,
                              void* d_out, int out_size)
{
    const int*   atom_ids = (const int*)  d_in[0];
    const int*   edge     = (const int*)  d_in[1];
    const int*   mol_ids  = (const int*)  d_in[2];
    const float* emb_W    = (const float*)d_in[3];
    const float* gin_W1   = (const float*)d_in[4];
    const float* gin_b1   = (const float*)d_in[5];
    const float* gin_g1   = (const float*)d_in[6];
    const float* gin_be1  = (const float*)d_in[7];
    const float* gin_W2   = (const float*)d_in[8];
    const float* gin_b2   = (const float*)d_in[9];
    const float* jk_W     = (const float*)d_in[10];
    const float* jk_b     = (const float*)d_in[11];
    const float* ffn_W1   = (const float*)d_in[12];
    const float* ffn_b1   = (const float*)d_in[13];
    const float* ffn_g    = (const float*)d_in[14];
    const float* ffn_be   = (const float*)d_in[15];
    const float* ffn_W2   = (const float*)d_in[16];
    const float* ffn_b2   = (const float*)d_in[17];
    const float* out_W    = (const float*)d_in[18];
    const float* out_b    = (const float*)d_in[19];
    float* out = (float*)d_out;

    const int* src = edge;
    const int* dst = edge + NE;

    float *X0, *T, *XS, *G, *TG, *stats;
    cudaGetSymbolAddress((void**)&X0,    g_X0);
    cudaGetSymbolAddress((void**)&T,     g_T);
    cudaGetSymbolAddress((void**)&XS,    g_XS);
    cudaGetSymbolAddress((void**)&G,     g_G);
    cudaGetSymbolAddress((void**)&TG,    g_TG);
    cudaGetSymbolAddress((void**)&stats, g_stats);

    cudaFuncSetAttribute(k_gemm<NT_GA,4,RPB_GA,1,0,0,1,1>,
                         cudaFuncAttributeMaxDynamicSharedMemorySize, SMEM_GA);
    cudaFuncSetAttribute(k_gemm<NT_NG,1,RPB_NG,0,1,1,0,1>,
                         cudaFuncAttributeMaxDynamicSharedMemorySize, SMEM_WB);
    cudaFuncSetAttribute(k_gemm<NT_NG,1,RPB_NG,0,0,0,0,NL>,
                         cudaFuncAttributeMaxDynamicSharedMemorySize, SMEM_WB);
    cudaFuncSetAttribute(k_gemm<NT_NG,1,RPB_NG,0,0,0,1,1>,
                         cudaFuncAttributeMaxDynamicSharedMemorySize, SMEM_WB);

    k_init<<<(NN + 255)/256, 256>>>();
    k_embed<<<(NN*16 + 255)/256, 256>>>(atom_ids, emb_W);
    {
        void* args[] = { (void*)&src, (void*)&dst };
        cudaLaunchCooperativeKernel((void*)k_csr_coop, dim3(COOP_BLOCKS), dim3(256),
                                    args, 0, (cudaStream_t)0);
    }

    const int GRID_GA = (NN + RPB_GA - 1) / RPB_GA;
    const int GRID_NG = (NN + RPB_NG - 1) / RPB_NG;
    for (int l = 0; l < NL; l++) {
        const float* xin = (l == 0) ? X0 : XS + (size_t)(l-1) * NN * D;
        float* slot = stats + (size_t)l * 2 * D;
        // gemm1: gather + GEMM + stats -> T   (320 threads, 80 rows, 4 blocks/SM)
        k_gemm<NT_GA,4,RPB_GA,1,0,0,1,1><<<GRID_GA, NT_GA, SMEM_GA>>>(
            xin, gin_W1 + (size_t)l*D*D, gin_b1 + l*D, T, NN,
            nullptr, slot, nullptr, nullptr, 0.f, 0, 0);
        // gemm2: direct-A BN+relu GEMM + relu -> XS[l]
        k_gemm<NT_NG,1,RPB_NG,0,1,1,0,1><<<GRID_NG, NT_NG, SMEM_WB>>>(
            T, gin_W2 + (size_t)l*D*D, gin_b2 + l*D, XS + (size_t)l*NN*D, NN,
            slot, nullptr, gin_g1 + l*D, gin_be1 + l*D, 1.0f / NN, 0, 0);
    }

    k_molptr<<<(NN + 255)/256, 256>>>(mol_ids);
    // JK: 3-pass accumulate -> X0
    k_gemm<NT_NG,1,RPB_NG,0,0,0,0,NL><<<GRID_NG, NT_NG, SMEM_WB>>>(
        XS, jk_W, jk_b, X0, NN,
        nullptr, nullptr, nullptr, nullptr, 0.f, (size_t)NN * D, (size_t)D * D);

    k_pool_seg<<<(NM*16 + 255)/256, 256>>>(X0);

    float* slot3 = stats + 3 * 2 * D;
    k_gemm<NT_NG,1,RPB_NG,0,0,0,1,1><<<(NM + RPB_NG - 1)/RPB_NG, NT_NG, SMEM_WB>>>(
        G, ffn_W1, ffn_b1, TG, NM,
        nullptr, slot3, nullptr, nullptr, 0.f, 0, 0);

    k_final<<<(NM + 255)/256, 256>>>(ffn_W2, out_W, ffn_b2, out_b,
                                     ffn_g, ffn_be, out, NM);
}

// round 17
// speedup vs baseline: 1.0558x; 1.0558x over previous
#include <cuda_runtime.h>
#include <cooperative_groups.h>
namespace cg = cooperative_groups;

#define NN 100000
#define NE 1200000
#define D 64
#define NL 3
#define NM 5000
#define NO 24
#define BN_EPS 1e-5f
#define NB_SCAN ((NN + 1023) / 1024)
#define HS 68
#define COOP_BLOCKS 592
#define SMEM_WB (2 * 2048 * 8)                   // 32768 B (W fragments hi+lo)
#define RPB_GA 96
#define NT_GA  384
#define SMEM_GA (RPB_GA * HS * 4 + SMEM_WB)      // 58880 B
#define RPB_NG 128
#define NT_NG  256
#define NWMAT 10                                  // precomputed fragment matrices

typedef unsigned long long ull;

// ---------------- scratch ----------------
__device__ __align__(128) float g_X0 [NN * D];
__device__ __align__(128) float g_T  [NN * D];
__device__ __align__(128) float g_XS [NL * NN * D];
__device__ __align__(128) float g_G  [NM * D];
__device__ __align__(128) float g_TG [NM * D];
__device__ __align__(128) float g_stats[4 * 2 * D];
__device__ __align__(128) ull g_wfrag[NWMAT * 4096];   // [mat][0..2047 hi | 2048..4095 lo]
__device__ __align__(128) int g_deg   [NN];
__device__ __align__(128) int g_cur   [NN];
__device__ __align__(128) int g_rowptr[NN + 1];
__device__ __align__(128) int g_csr   [NE];      // stores src*64 (pre-scaled)
__device__ __align__(128) int g_bsum  [NB_SCAN];
__device__ __align__(128) int g_boff  [NB_SCAN];
__device__ __align__(128) int g_molptr[NM + 1];

// ---------------- helpers ----------------
__device__ __forceinline__ uint32_t cvt_tf32(float x) {
    uint32_t r; asm("cvt.rna.tf32.f32 %0, %1;" : "=r"(r) : "f"(x)); return r;
}
__device__ __forceinline__ void mma_tf32(float* c, uint32_t a0, uint32_t a1,
                                         uint32_t a2, uint32_t a3,
                                         uint32_t b0, uint32_t b1) {
    asm volatile(
        "mma.sync.aligned.m16n8k8.row.col.f32.tf32.tf32.f32 "
        "{%0,%1,%2,%3},{%4,%5,%6,%7},{%8,%9},{%0,%1,%2,%3};"
        : "+f"(c[0]), "+f"(c[1]), "+f"(c[2]), "+f"(c[3])
        : "r"(a0), "r"(a1), "r"(a2), "r"(a3), "r"(b0), "r"(b1));
}

// ---------------- init ----------------
__global__ void k_init() {
    int t = blockIdx.x * blockDim.x + threadIdx.x;
    if (t < NN) { g_deg[t] = 0; g_cur[t] = 0; }
    if (t < 4 * 2 * D) g_stats[t] = 0.f;
}

__global__ void k_embed(const int* __restrict__ atom_ids, const float* __restrict__ embW) {
    int t = blockIdx.x * blockDim.x + threadIdx.x;
    if (t >= NN * 16) return;
    int n = t >> 4, c = (t & 15) << 2;
    int a = __ldg(atom_ids + n);
    *(float4*)(g_X0 + (size_t)n * D + c) = *(const float4*)(embW + (size_t)a * D + c);
}

// ---------------- precompute W fragments (one block per matrix) -------------
__global__ void k_wfrag(const float* __restrict__ gin_W1, const float* __restrict__ gin_W2,
                        const float* __restrict__ jk_W,   const float* __restrict__ ffn_W1) {
    int m = blockIdx.x;
    const float* Wp;
    if (m < 3)       Wp = gin_W1 + (size_t)m * D * D;
    else if (m < 6)  Wp = gin_W2 + (size_t)(m - 3) * D * D;
    else if (m < 9)  Wp = jk_W   + (size_t)(m - 6) * D * D;
    else             Wp = ffn_W1;
    ull* out = g_wfrag + (size_t)m * 4096;
    for (int i = threadIdx.x; i < 2048; i += blockDim.x) {
        int ent = i >> 5, ll = i & 31;
        int ks = ent >> 3, nt = ent & 7;
        int k0 = ks * 8 + (ll & 3), n = nt * 8 + (ll >> 2);
        float w0 = __ldg(&Wp[k0 * D + n]);
        float w1 = __ldg(&Wp[(k0 + 4) * D + n]);
        uint32_t h0 = cvt_tf32(w0), h1 = cvt_tf32(w1);
        uint32_t l0 = cvt_tf32(w0 - __uint_as_float(h0));
        uint32_t l1 = cvt_tf32(w1 - __uint_as_float(h1));
        out[i]        = (ull)h0 | ((ull)h1 << 32);
        out[2048 + i] = (ull)l0 | ((ull)l1 << 32);
    }
}

// ---------------- cooperative CSR build -----------------
__global__ void k_csr_coop(const int* __restrict__ src, const int* __restrict__ dst) {
    cg::grid_group grid = cg::this_grid();
    int tid = threadIdx.x, bid = blockIdx.x;
    int gt = bid * 256 + tid, gs = gridDim.x * 256;

    for (int e = gt; e < NE; e += gs) atomicAdd(&g_deg[__ldg(dst + e)], 1);
    grid.sync();

    __shared__ int sh[256];
    if (bid < NB_SCAN) {
        int base = bid * 1024;
        int loc[4]; int s = 0;
        #pragma unroll
        for (int j = 0; j < 4; j++) {
            int i = base + tid * 4 + j;
            int v = (i < NN) ? g_deg[i] : 0;
            s += v; loc[j] = s;
        }
        int excl_in = s;
        sh[tid] = excl_in; __syncthreads();
        for (int off = 1; off < 256; off <<= 1) {
            int t2 = (tid >= off) ? sh[tid - off] : 0;
            __syncthreads();
            sh[tid] += t2;
            __syncthreads();
        }
        int pre = sh[tid] - excl_in;
        #pragma unroll
        for (int j = 0; j < 4; j++) {
            int i = base + tid * 4 + j;
            if (i < NN) g_rowptr[i + 1] = pre + loc[j];
        }
        if (tid == 255) g_bsum[bid] = sh[255];
    }
    grid.sync();

    if (bid == 0 && tid < 32) {
        int carry = 0;
        for (int b = 0; b < NB_SCAN; b += 32) {
            int idx = b + tid;
            int v = (idx < NB_SCAN) ? g_bsum[idx] : 0;
            int x = v;
            #pragma unroll
            for (int off = 1; off < 32; off <<= 1) {
                int y = __shfl_up_sync(0xffffffff, x, off);
                if (tid >= off) x += y;
            }
            if (idx < NB_SCAN) g_boff[idx] = carry + x - v;
            carry += __shfl_sync(0xffffffff, x, 31);
        }
    }
    grid.sync();

    if (gt == 0) g_rowptr[0] = 0;
    for (int i = gt; i < NN; i += gs) g_rowptr[i + 1] += g_boff[i >> 10];
    grid.sync();

    for (int e = gt; e < NE; e += gs) {
        int d = __ldg(dst + e);
        int pos = g_rowptr[d] + atomicAdd(&g_cur[d], 1);
        g_csr[pos] = __ldg(src + e) << 6;      // pre-scaled by D
    }
}

__global__ void k_molptr(const int* __restrict__ mol) {
    int t = blockIdx.x * blockDim.x + threadIdx.x;
    if (t >= NN) return;
    int m1 = __ldg(mol + t);
    int m0 = (t == 0) ? -1 : __ldg(mol + t - 1);
    for (int m = m0 + 1; m <= m1; m++) g_molptr[m] = t;
    if (t == NN - 1)
        for (int m = m1 + 1; m <= NM; m++) g_molptr[m] = NN;
}

// ============================================================================
// Unified GEMM kernel (mma.sync tf32, 3xTF32). W fragments precomputed in
// g_wfrag; per-block staging is a plain 32KB copy.
// ============================================================================
template<int NT, int RPBt, int GATHER, int IN_BN, int OUT_RELU, int STATS, int NPASS>
__global__ __launch_bounds__(NT) void k_gemm(
    const float* __restrict__ X, const ull* __restrict__ Wfrag,
    const float* __restrict__ bias, float* __restrict__ O, int rows,
    const float* __restrict__ statsIn, float* __restrict__ statsOut,
    const float* __restrict__ gg, const float* __restrict__ be, float inv_n,
    size_t xStride)
{
    constexpr int NWARP = NT / 32;
    constexpr int NMT   = RPBt / 16;
    constexpr int WPT   = NWARP / NMT;
    constexpr int NTN   = 8 / WPT;

    extern __shared__ __align__(16) float dsm[];
    float* Hs  = dsm;
    ull*   WBh = (ull*)(GATHER ? (dsm + RPBt * HS) : dsm);
    ull*   WBl = WBh + 2048;
    __shared__ float ssa[D], ssb[D];
    __shared__ float sbuf[2 * D];
    __shared__ int   rp[RPB_NG + 1];
    int tid = threadIdx.x;
    int base = blockIdx.x * RPBt;
    int w = tid >> 5, l = tid & 31;
    int g = l >> 2, t = l & 3;
    int mt = w / WPT, nt0 = (w % WPT) * NTN;

    if (IN_BN && tid < D) {
        float mu  = statsIn[tid] * inv_n;
        float var = statsIn[D + tid] * inv_n - mu * mu;
        float rs  = rsqrtf(var + BN_EPS);
        float a   = rs * gg[tid];
        ssa[tid] = a; ssb[tid] = be[tid] - mu * a;
    }
    if (STATS && tid < 2 * D) sbuf[tid] = 0.f;
    if (GATHER && tid <= RPBt) {
        int node = base + tid;
        rp[tid] = (node <= rows) ? __ldg(&g_rowptr[node]) : 0;
    }

    float c[NTN][4];
    #pragma unroll
    for (int q = 0; q < NTN; q++) {
        float2 b2 = *(const float2*)(bias + (nt0 + q) * 8 + 2 * t);
        c[q][0] = b2.x; c[q][1] = b2.y; c[q][2] = b2.x; c[q][3] = b2.y;
    }

    int r0g = base + mt * 16 + g, r1g = r0g + 8;
    bool v0 = (r0g < rows), v1 = (r1g < rows);

    for (int ps = 0; ps < NPASS; ps++) {
        __syncthreads();
        // ---- stage W fragments: plain copy from precomputed global ----
        {
            const ull* Wp = Wfrag + (size_t)ps * 4096;
            for (int i = tid; i < 2048; i += NT) {
                WBh[i] = __ldg(&Wp[i]);
                WBl[i] = __ldg(&Wp[2048 + i]);
            }
        }
        // ---- stage Hs (gather) ----
        if (GATHER) {
            constexpr int NPB = NT / 16;
            constexpr int NB  = RPBt * 16 / NT;
            int cc = (tid & 15) << 2;
            #pragma unroll
            for (int b = 0; b < NB; b++) {
                int n = b * NPB + (tid >> 4);
                int node = base + n;
                if (node < rows) {
                    int beg = rp[n], end = rp[n + 1];
                    float4 acc = *(const float4*)(X + (size_t)node * D + cc);
                    int e = beg;
                    int i0, i1, i2, i3;
                    bool have = (e + 3 < end);
                    if (have) {
                        i0 = __ldg(&g_csr[e]);     i1 = __ldg(&g_csr[e + 1]);
                        i2 = __ldg(&g_csr[e + 2]); i3 = __ldg(&g_csr[e + 3]);
                    }
                    while (have) {
                        int en = e + 4;
                        bool hn = (en + 3 < end);
                        int j0, j1, j2, j3;
                        if (hn) {
                            j0 = __ldg(&g_csr[en]);     j1 = __ldg(&g_csr[en + 1]);
                            j2 = __ldg(&g_csr[en + 2]); j3 = __ldg(&g_csr[en + 3]);
                        }
                        float4 v0f = *(const float4*)(X + (size_t)(i0 + cc));
                        float4 v1f = *(const float4*)(X + (size_t)(i1 + cc));
                        float4 v2f = *(const float4*)(X + (size_t)(i2 + cc));
                        float4 v3f = *(const float4*)(X + (size_t)(i3 + cc));
                        acc.x += (v0f.x + v1f.x) + (v2f.x + v3f.x);
                        acc.y += (v0f.y + v1f.y) + (v2f.y + v3f.y);
                        acc.z += (v0f.z + v1f.z) + (v2f.z + v3f.z);
                        acc.w += (v0f.w + v1f.w) + (v2f.w + v3f.w);
                        e = en; have = hn;
                        i0 = j0; i1 = j1; i2 = j2; i3 = j3;
                    }
                    for (; e < end; e++) {
                        int s0 = __ldg(&g_csr[e]);
                        float4 v0f = *(const float4*)(X + (size_t)(s0 + cc));
                        acc.x += v0f.x; acc.y += v0f.y; acc.z += v0f.z; acc.w += v0f.w;
                    }
                    *(float4*)(Hs + n * HS + cc) = acc;
                }
            }
        }
        __syncthreads();

        // ---- MMA mainloop ----
        const float* ar0 = GATHER ? (Hs + (mt * 16 + g) * HS) : nullptr;
        const float* ar1 = GATHER ? (ar0 + 8 * HS) : nullptr;
        const float* Xr0 = GATHER ? nullptr : (X + (size_t)ps * xStride + (size_t)r0g * D);
        const float* Xr1 = GATHER ? nullptr : (X + (size_t)ps * xStride + (size_t)r1g * D);
        #pragma unroll
        for (int ks = 0; ks < 8; ks++) {
            int kc = ks * 8 + t;
            float x00, x01, x10, x11;
            if (GATHER) {
                x00 = ar0[kc]; x01 = ar0[kc + 4];
                x10 = ar1[kc]; x11 = ar1[kc + 4];
            } else {
                x00 = v0 ? __ldg(Xr0 + kc)     : 0.f;
                x01 = v0 ? __ldg(Xr0 + kc + 4) : 0.f;
                x10 = v1 ? __ldg(Xr1 + kc)     : 0.f;
                x11 = v1 ? __ldg(Xr1 + kc + 4) : 0.f;
                if (IN_BN) {
                    x00 = fmaxf(x00 * ssa[kc]     + ssb[kc],     0.f);
                    x01 = fmaxf(x01 * ssa[kc + 4] + ssb[kc + 4], 0.f);
                    x10 = fmaxf(x10 * ssa[kc]     + ssb[kc],     0.f);
                    x11 = fmaxf(x11 * ssa[kc + 4] + ssb[kc + 4], 0.f);
                }
            }
            uint32_t ah0 = cvt_tf32(x00), ah1 = cvt_tf32(x10);
            uint32_t ah2 = cvt_tf32(x01), ah3 = cvt_tf32(x11);
            uint32_t al0 = cvt_tf32(x00 - __uint_as_float(ah0));
            uint32_t al1 = cvt_tf32(x10 - __uint_as_float(ah1));
            uint32_t al2 = cvt_tf32(x01 - __uint_as_float(ah2));
            uint32_t al3 = cvt_tf32(x11 - __uint_as_float(ah3));
            #pragma unroll
            for (int q = 0; q < NTN; q++) {
                int nt = nt0 + q;
                ull bh = WBh[(ks * 8 + nt) * 32 + l];
                ull bl = WBl[(ks * 8 + nt) * 32 + l];
                uint32_t bh0 = (uint32_t)bh, bh1 = (uint32_t)(bh >> 32);
                uint32_t bl0 = (uint32_t)bl, bl1 = (uint32_t)(bl >> 32);
                mma_tf32(c[q], ah0, ah1, ah2, ah3, bh0, bh1);
                mma_tf32(c[q], al0, al1, al2, al3, bh0, bh1);
                mma_tf32(c[q], ah0, ah1, ah2, ah3, bl0, bl1);
            }
        }
    }

    // ---- store ----
    #pragma unroll
    for (int q = 0; q < NTN; q++) {
        int col = (nt0 + q) * 8 + 2 * t;
        if (v0) {
            float2 o = make_float2(c[q][0], c[q][1]);
            if (OUT_RELU) { o.x = fmaxf(o.x, 0.f); o.y = fmaxf(o.y, 0.f); }
            *(float2*)(O + (size_t)r0g * D + col) = o;
        }
        if (v1) {
            float2 o = make_float2(c[q][2], c[q][3]);
            if (OUT_RELU) { o.x = fmaxf(o.x, 0.f); o.y = fmaxf(o.y, 0.f); }
            *(float2*)(O + (size_t)r1g * D + col) = o;
        }
    }

    if (STATS) {
        #pragma unroll
        for (int q = 0; q < NTN; q++) {
            float e0 = v0 ? c[q][0] : 0.f, e1 = v0 ? c[q][1] : 0.f;
            float e2 = v1 ? c[q][2] : 0.f, e3 = v1 ? c[q][3] : 0.f;
            float s0 = e0 + e2, s1 = e1 + e3;
            float q0 = e0 * e0 + e2 * e2, q1 = e1 * e1 + e3 * e3;
            #pragma unroll
            for (int off = 4; off < 32; off <<= 1) {
                s0 += __shfl_xor_sync(0xffffffff, s0, off);
                s1 += __shfl_xor_sync(0xffffffff, s1, off);
                q0 += __shfl_xor_sync(0xffffffff, q0, off);
                q1 += __shfl_xor_sync(0xffffffff, q1, off);
            }
            if (l < 4) {
                int col = (nt0 + q) * 8 + 2 * t;
                atomicAdd(&sbuf[col],         s0);
                atomicAdd(&sbuf[col + 1],     s1);
                atomicAdd(&sbuf[D + col],     q0);
                atomicAdd(&sbuf[D + col + 1], q1);
            }
        }
        __syncthreads();
        if (tid < 2 * D) atomicAdd(&statsOut[tid], sbuf[tid]);
    }
}

// segmented pool
__global__ void k_pool_seg(const float* __restrict__ XJ) {
    int t = blockIdx.x * 256 + threadIdx.x;
    int m = t >> 4;
    if (m >= NM) return;
    int c = (t & 15) << 2;
    int beg = g_molptr[m], end = g_molptr[m + 1];
    float4 acc = make_float4(0.f, 0.f, 0.f, 0.f);
    for (int n = beg; n < end; n++) {
        float4 v = *(const float4*)(XJ + (size_t)n * D + c);
        acc.x += v.x; acc.y += v.y; acc.z += v.z; acc.w += v.w;
    }
    *(float4*)(g_G + (size_t)m * D + c) = acc;
}

// out = relu(TG*bn) @ (W2 @ oW) + (b2 @ oW + ob)
__global__ __launch_bounds__(256) void k_final(
    const float* __restrict__ W2, const float* __restrict__ oW,
    const float* __restrict__ b2, const float* __restrict__ ob,
    const float* __restrict__ gg, const float* __restrict__ be,
    float* __restrict__ out, int rows)
{
    __shared__ float Ws[D * NO];
    __shared__ float bcs[NO], sa[D], sb[D];
    int tid = threadIdx.x;
    const float* statsIn = g_stats + 3 * 2 * D;
    for (int i = tid; i < D * NO; i += 256) {
        int k = i / NO, o = i % NO;
        float sum = 0.f;
        for (int j = 0; j < D; j++) sum += W2[k * D + j] * oW[j * NO + o];
        Ws[i] = sum;
    }
    if (tid < NO) {
        float sum = ob[tid];
        for (int j = 0; j < D; j++) sum += b2[j] * oW[j * NO + tid];
        bcs[tid] = sum;
    }
    if (tid < D) {
        float mu  = statsIn[tid] * (1.0f / NM);
        float var = statsIn[D + tid] * (1.0f / NM) - mu * mu;
        float rs  = rsqrtf(var + BN_EPS);
        float a   = rs * gg[tid];
        sa[tid] = a; sb[tid] = be[tid] - mu * a;
    }
    __syncthreads();
    int row = blockIdx.x * 256 + tid;
    if (row >= rows) return;
    float acc[NO];
    #pragma unroll
    for (int o = 0; o < NO; o++) acc[o] = bcs[o];
    const float* tr = g_TG + (size_t)row * D;
    for (int k = 0; k < D; k++) {
        float h = fmaxf(tr[k] * sa[k] + sb[k], 0.f);
        #pragma unroll
        for (int o = 0; o < NO; o++) acc[o] += h * Ws[k * NO + o];
    }
    float* orow = out + (size_t)row * NO;
    #pragma unroll
    for (int o = 0; o < NO; o++) orow[o] = acc[o];
}

// ---------------- host ----------------
extern "C" void kernel_launch(void* const* d_in, const int* in_sizes, int n_in,
                              void* d_out, int out_size)
{
    const int*   atom_ids = (const int*)  d_in[0];
    const int*   edge     = (const int*)  d_in[1];
    const int*   mol_ids  = (const int*)  d_in[2];
    const float* emb_W    = (const float*)d_in[3];
    const float* gin_W1   = (const float*)d_in[4];
    const float* gin_b1   = (const float*)d_in[5];
    const float* gin_g1   = (const float*)d_in[6];
    const float* gin_be1  = (const float*)d_in[7];
    const float* gin_W2   = (const float*)d_in[8];
    const float* gin_b2   = (const float*)d_in[9];
    const float* jk_W     = (const float*)d_in[10];
    const float* jk_b     = (const float*)d_in[11];
    const float* ffn_W1   = (const float*)d_in[12];
    const float* ffn_b1   = (const float*)d_in[13];
    const float* ffn_g    = (const float*)d_in[14];
    const float* ffn_be   = (const float*)d_in[15];
    const float* ffn_W2   = (const float*)d_in[16];
    const float* ffn_b2   = (const float*)d_in[17];
    const float* out_W    = (const float*)d_in[18];
    const float* out_b    = (const float*)d_in[19];
    float* out = (float*)d_out;

    const int* src = edge;
    const int* dst = edge + NE;

    float *X0, *T, *XS, *G, *TG, *stats;
    ull* wfrag;
    cudaGetSymbolAddress((void**)&X0,    g_X0);
    cudaGetSymbolAddress((void**)&T,     g_T);
    cudaGetSymbolAddress((void**)&XS,    g_XS);
    cudaGetSymbolAddress((void**)&G,     g_G);
    cudaGetSymbolAddress((void**)&TG,    g_TG);
    cudaGetSymbolAddress((void**)&stats, g_stats);
    cudaGetSymbolAddress((void**)&wfrag, g_wfrag);

    cudaFuncSetAttribute(k_gemm<NT_GA,RPB_GA,1,0,0,1,1>,
                         cudaFuncAttributeMaxDynamicSharedMemorySize, SMEM_GA);
    cudaFuncSetAttribute(k_gemm<NT_NG,RPB_NG,0,1,1,0,1>,
                         cudaFuncAttributeMaxDynamicSharedMemorySize, SMEM_WB);
    cudaFuncSetAttribute(k_gemm<NT_NG,RPB_NG,0,0,0,0,NL>,
                         cudaFuncAttributeMaxDynamicSharedMemorySize, SMEM_WB);
    cudaFuncSetAttribute(k_gemm<NT_NG,RPB_NG,0,0,0,1,1>,
                         cudaFuncAttributeMaxDynamicSharedMemorySize, SMEM_WB);

    k_init<<<(NN + 255)/256, 256>>>();
    k_embed<<<(NN*16 + 255)/256, 256>>>(atom_ids, emb_W);
    k_wfrag<<<NWMAT, 256>>>(gin_W1, gin_W2, jk_W, ffn_W1);
    {
        void* args[] = { (void*)&src, (void*)&dst };
        cudaLaunchCooperativeKernel((void*)k_csr_coop, dim3(COOP_BLOCKS), dim3(256),
                                    args, 0, (cudaStream_t)0);
    }

    const int GRID_GA = (NN + RPB_GA - 1) / RPB_GA;
    const int GRID_NG = (NN + RPB_NG - 1) / RPB_NG;
    for (int l = 0; l < NL; l++) {
        const float* xin = (l == 0) ? X0 : XS + (size_t)(l-1) * NN * D;
        float* slot = stats + (size_t)l * 2 * D;
        // gemm1: gather + GEMM + stats -> T   (384 threads, 96 rows)
        k_gemm<NT_GA,RPB_GA,1,0,0,1,1><<<GRID_GA, NT_GA, SMEM_GA>>>(
            xin, wfrag + (size_t)l * 4096, gin_b1 + l*D, T, NN,
            nullptr, slot, nullptr, nullptr, 0.f, 0);
        // gemm2: direct-A BN+relu GEMM + relu -> XS[l]
        k_gemm<NT_NG,RPB_NG,0,1,1,0,1><<<GRID_NG, NT_NG, SMEM_WB>>>(
            T, wfrag + (size_t)(3 + l) * 4096, gin_b2 + l*D, XS + (size_t)l*NN*D, NN,
            slot, nullptr, gin_g1 + l*D, gin_be1 + l*D, 1.0f / NN, 0);
    }

    k_molptr<<<(NN + 255)/256, 256>>>(mol_ids);
    // JK: 3-pass accumulate -> X0 (fragment matrices 6,7,8 are consecutive)
    k_gemm<NT_NG,RPB_NG,0,0,0,0,NL><<<GRID_NG, NT_NG, SMEM_WB>>>(
        XS, wfrag + (size_t)6 * 4096, jk_b, X0, NN,
        nullptr, nullptr, nullptr, nullptr, 0.f, (size_t)NN * D);

    k_pool_seg<<<(NM*16 + 255)/256, 256>>>(X0);

    float* slot3 = stats + 3 * 2 * D;
    k_gemm<NT_NG,RPB_NG,0,0,0,1,1><<<(NM + RPB_NG - 1)/RPB_NG, NT_NG, SMEM_WB>>>(
        G, wfrag + (size_t)9 * 4096, ffn_b1, TG, NM,
        nullptr, slot3, nullptr, nullptr, 0.f, 0);

    k_final<<<(NM + 255)/256, 256>>>(ffn_W2, out_W, ffn_b2, out_b,
                                     ffn_g, ffn_be, out, NM);
}